// round 1
// baseline (speedup 1.0000x reference)
#include <cuda_runtime.h>

// Problem constants
constexpr int B_   = 4;
constexpr int S_   = 1024;
constexpr int HID_ = 1024;
constexpr int H_   = 16;
constexpr int D_   = 64;

// Scratch for projected Q/K in [b, h, s, d] layout (float4 for 16B alignment)
__device__ float4 g_q4[(size_t)B_ * H_ * S_ * D_ / 4];
__device__ float4 g_k4[(size_t)B_ * H_ * S_ * D_ / 4];

// ---------------------------------------------------------------------------
// Kernel 1: fused Q/K projection GEMM.
//   C[m, n] = sum_k hidden[m, k] * W[n, k]
//   m in [0, B*S) = 4096, n in [0, 2*HID) = 2048 (first half Wq -> q, second Wk -> k)
// Output written directly in [b, h, s, d] layout into g_q4 / g_k4.
// Tiles: 128x128 block, BK=16, 256 threads, 8x8 register microtile.
// ---------------------------------------------------------------------------
__global__ __launch_bounds__(256) void proj_kernel(
    const float* __restrict__ hidden,
    const float* __restrict__ Wq,
    const float* __restrict__ Wk)
{
    __shared__ float As[16][128];   // [k][m]  (transposed for broadcast reads)
    __shared__ float Ws[16][128];   // [k][n]

    const int col0  = blockIdx.x * 128;            // n tile base (0..2047)
    const int row0  = blockIdx.y * 128;            // m tile base (0..4095)
    const float* W  = (col0 < HID_) ? Wq : Wk;
    float* outp     = (col0 < HID_) ? (float*)g_q4 : (float*)g_k4;
    const int wcol0 = col0 & (HID_ - 1);

    const int tid = threadIdx.x;
    const int tx  = tid & 15;
    const int ty  = tid >> 4;

    float acc[8][8];
    #pragma unroll
    for (int i = 0; i < 8; i++)
        #pragma unroll
        for (int j = 0; j < 8; j++) acc[i][j] = 0.f;

    for (int k0 = 0; k0 < HID_; k0 += 16) {
        // Load A tile (128 rows x 16 k) and W tile (128 cols x 16 k), transposed.
        #pragma unroll
        for (int p = 0; p < 2; p++) {
            int idx = tid + p * 256;           // 0..511
            int m   = idx >> 2;                // 0..127
            int kq  = (idx & 3) * 4;           // 0,4,8,12
            float4 va = *(const float4*)(hidden + (size_t)(row0 + m) * HID_ + k0 + kq);
            As[kq + 0][m] = va.x; As[kq + 1][m] = va.y;
            As[kq + 2][m] = va.z; As[kq + 3][m] = va.w;
            float4 vw = *(const float4*)(W + (size_t)(wcol0 + m) * HID_ + k0 + kq);
            Ws[kq + 0][m] = vw.x; Ws[kq + 1][m] = vw.y;
            Ws[kq + 2][m] = vw.z; Ws[kq + 3][m] = vw.w;
        }
        __syncthreads();

        #pragma unroll
        for (int k = 0; k < 16; k++) {
            float a[8], b[8];
            *(float4*)(a)     = *(const float4*)&As[k][ty * 8];
            *(float4*)(a + 4) = *(const float4*)&As[k][ty * 8 + 4];
            *(float4*)(b)     = *(const float4*)&Ws[k][tx * 8];
            *(float4*)(b + 4) = *(const float4*)&Ws[k][tx * 8 + 4];
            #pragma unroll
            for (int i = 0; i < 8; i++)
                #pragma unroll
                for (int j = 0; j < 8; j++)
                    acc[i][j] = fmaf(a[i], b[j], acc[i][j]);
        }
        __syncthreads();
    }

    // Epilogue: scatter into [b, h, s, d] layout (8 consecutive n stay within one head).
    #pragma unroll
    for (int i = 0; i < 8; i++) {
        int m = row0 + ty * 8 + i;
        int b = m >> 10;            // / S_
        int s = m & (S_ - 1);
        #pragma unroll
        for (int j4 = 0; j4 < 2; j4++) {
            int nloc = wcol0 + tx * 8 + j4 * 4;
            int h = nloc >> 6;      // / D_
            int d = nloc & 63;
            float4 v = make_float4(acc[i][j4 * 4 + 0], acc[i][j4 * 4 + 1],
                                   acc[i][j4 * 4 + 2], acc[i][j4 * 4 + 3]);
            *(float4*)(outp + (((size_t)(b * H_ + h) * S_ + s) * D_ + d)) = v;
        }
    }
}

// ---------------------------------------------------------------------------
// Kernel 2: RoPE applied in place to g_q / g_k.
// Thread handles one (row, d2) pair with d2 in [0, 32): rotates (d2, d2+32).
// cos/sin layout: (1,1,S,D) with cos[s, d] == cos[s, d % 32] duplicated halves.
// ---------------------------------------------------------------------------
__global__ __launch_bounds__(256) void rope_kernel(
    const float* __restrict__ cosp,
    const float* __restrict__ sinp)
{
    int idx = blockIdx.x * blockDim.x + threadIdx.x;   // 0 .. B*H*S*32
    int d2     = idx & 31;
    int rowidx = idx >> 5;              // (b*H + h)*S + s
    int s      = rowidx & (S_ - 1);

    float c  = cosp[s * D_ + d2];
    float sn = sinp[s * D_ + d2];

    float* gq = (float*)g_q4;
    float* gk = (float*)g_k4;
    size_t base = (size_t)rowidx * D_;

    float q1 = gq[base + d2], q2 = gq[base + d2 + 32];
    gq[base + d2]      = fmaf(q1, c, -q2 * sn);
    gq[base + d2 + 32] = fmaf(q2, c,  q1 * sn);

    float k1 = gk[base + d2], k2 = gk[base + d2 + 32];
    gk[base + d2]      = fmaf(k1, c, -k2 * sn);
    gk[base + d2 + 32] = fmaf(k2, c,  k1 * sn);
}

// ---------------------------------------------------------------------------
// Kernel 3: scores GEMM.  scores[bh, qi, kj] = (q . k) / 8, written raw to d_out.
// Fully-masked tiles (k0 > q0 + 127) are skipped entirely: the softmax kernel
// never reads kj > qi and writes zeros there itself.
// Tiles: 128x128 per block over a K=64 reduction (two chunks of 32 in smem).
// ---------------------------------------------------------------------------
__global__ __launch_bounds__(256) void scores_kernel(float* __restrict__ out)
{
    const int bxt = blockIdx.x;   // k tile
    const int byt = blockIdx.y;   // q tile
    if (bxt > byt) return;        // fully above the causal diagonal -> skip

    const int bh = blockIdx.z;
    const int q0 = byt * 128;
    const int k0 = bxt * 128;
    const float* Qp = (const float*)g_q4 + (size_t)bh * S_ * D_;
    const float* Kp = (const float*)g_k4 + (size_t)bh * S_ * D_;

    __shared__ float Qs[32][128];   // [d][qi]
    __shared__ float Ks[32][128];   // [d][kj]

    const int tid = threadIdx.x;
    const int tx  = tid & 15;
    const int ty  = tid >> 4;

    float acc[8][8];
    #pragma unroll
    for (int i = 0; i < 8; i++)
        #pragma unroll
        for (int j = 0; j < 8; j++) acc[i][j] = 0.f;

    for (int c0 = 0; c0 < D_; c0 += 32) {
        #pragma unroll
        for (int p = 0; p < 4; p++) {
            int idx = tid + p * 256;    // 0..1023
            int m   = idx >> 3;         // 0..127
            int dq  = (idx & 7) * 4;    // 0..28
            float4 vq = *(const float4*)(Qp + (size_t)(q0 + m) * D_ + c0 + dq);
            Qs[dq + 0][m] = vq.x; Qs[dq + 1][m] = vq.y;
            Qs[dq + 2][m] = vq.z; Qs[dq + 3][m] = vq.w;
            float4 vk = *(const float4*)(Kp + (size_t)(k0 + m) * D_ + c0 + dq);
            Ks[dq + 0][m] = vk.x; Ks[dq + 1][m] = vk.y;
            Ks[dq + 2][m] = vk.z; Ks[dq + 3][m] = vk.w;
        }
        __syncthreads();

        #pragma unroll
        for (int d = 0; d < 32; d++) {
            float a[8], b[8];
            *(float4*)(a)     = *(const float4*)&Qs[d][ty * 8];
            *(float4*)(a + 4) = *(const float4*)&Qs[d][ty * 8 + 4];
            *(float4*)(b)     = *(const float4*)&Ks[d][tx * 8];
            *(float4*)(b + 4) = *(const float4*)&Ks[d][tx * 8 + 4];
            #pragma unroll
            for (int i = 0; i < 8; i++)
                #pragma unroll
                for (int j = 0; j < 8; j++)
                    acc[i][j] = fmaf(a[i], b[j], acc[i][j]);
        }
        __syncthreads();
    }

    // Write raw scaled scores (values above the diagonal are ignored downstream).
    #pragma unroll
    for (int i = 0; i < 8; i++) {
        size_t rbase = ((size_t)bh * S_ + (q0 + ty * 8 + i)) * S_ + k0 + tx * 8;
        #pragma unroll
        for (int j4 = 0; j4 < 2; j4++) {
            float4 v = make_float4(acc[i][j4 * 4 + 0] * 0.125f,
                                   acc[i][j4 * 4 + 1] * 0.125f,
                                   acc[i][j4 * 4 + 2] * 0.125f,
                                   acc[i][j4 * 4 + 3] * 0.125f);
            *(float4*)(out + rbase + j4 * 4) = v;
        }
    }
}

// ---------------------------------------------------------------------------
// Kernel 4: causal softmax, in place over rows of d_out.
// One block (256 threads) per row; reads only kj <= qi, writes full 1024-row
// (zeros above the diagonal -> matches reference exactly: exp(min - max) == 0).
// ---------------------------------------------------------------------------
__global__ __launch_bounds__(256) void softmax_kernel(float* __restrict__ out)
{
    __shared__ float red[8];

    const int row = blockIdx.x;            // bh*S + qi
    const int qi  = row & (S_ - 1);
    const int nvalid = qi + 1;
    float* rp = out + (size_t)row * S_;

    const int tid  = threadIdx.x;
    const int base = tid * 4;

    float x[4] = {0.f, 0.f, 0.f, 0.f};
    if (base < nvalid) {
        float4 v = *(const float4*)(rp + base);
        x[0] = v.x; x[1] = v.y; x[2] = v.z; x[3] = v.w;
    }

    float mx = -3.402823466e38f;
    #pragma unroll
    for (int c = 0; c < 4; c++)
        if (base + c < nvalid) mx = fmaxf(mx, x[c]);

    #pragma unroll
    for (int o = 16; o > 0; o >>= 1)
        mx = fmaxf(mx, __shfl_xor_sync(0xFFFFFFFFu, mx, o));
    if ((tid & 31) == 0) red[tid >> 5] = mx;
    __syncthreads();

    float allmax = red[0];
    #pragma unroll
    for (int w = 1; w < 8; w++) allmax = fmaxf(allmax, red[w]);
    __syncthreads();   // before reusing red[] for the sum

    float e[4];
    float ssum = 0.f;
    #pragma unroll
    for (int c = 0; c < 4; c++) {
        e[c] = (base + c < nvalid) ? __expf(x[c] - allmax) : 0.f;
        ssum += e[c];
    }

    #pragma unroll
    for (int o = 16; o > 0; o >>= 1)
        ssum += __shfl_xor_sync(0xFFFFFFFFu, ssum, o);
    if ((tid & 31) == 0) red[tid >> 5] = ssum;
    __syncthreads();

    float tot = red[0];
    #pragma unroll
    for (int w = 1; w < 8; w++) tot += red[w];
    float inv = 1.0f / tot;

    float4 o4 = make_float4(e[0] * inv, e[1] * inv, e[2] * inv, e[3] * inv);
    *(float4*)(rp + base) = o4;
}

// ---------------------------------------------------------------------------
// Launch. Inputs (metadata order): hidden_states, cos, sin, attention_mask,
// Wq, Wk. The mask is the deterministic causal mask, so it is ignored and the
// weights are taken as the last two inputs (robust to mask dtype handling).
// ---------------------------------------------------------------------------
extern "C" void kernel_launch(void* const* d_in, const int* in_sizes, int n_in,
                              void* d_out, int out_size)
{
    const float* hidden = (const float*)d_in[0];
    const float* cosp   = (const float*)d_in[1];
    const float* sinp   = (const float*)d_in[2];
    const float* Wq     = (const float*)d_in[n_in - 2];
    const float* Wk     = (const float*)d_in[n_in - 1];
    float* out          = (float*)d_out;

    // 1. Q/K projection GEMM (N = 2*HID covers both weight matrices)
    dim3 g1((2 * HID_) / 128, (B_ * S_) / 128);
    proj_kernel<<<g1, 256>>>(hidden, Wq, Wk);

    // 2. RoPE in place
    rope_kernel<<<(B_ * H_ * S_ * 32) / 256, 256>>>(cosp, sinp);

    // 3. Scores GEMM -> raw scores in d_out (lower-triangular tiles only)
    dim3 g2(S_ / 128, S_ / 128, B_ * H_);
    scores_kernel<<<g2, 256>>>(out);

    // 4. Causal softmax in place
    softmax_kernel<<<B_ * H_ * S_, 256>>>(out);
}

// round 3
// speedup vs baseline: 1.5809x; 1.5809x over previous
#include <cuda_runtime.h>
#include <cuda_bf16.h>
#include <mma.h>
#include <cstdint>

using namespace nvcuda;

// Problem constants
constexpr int B_   = 4;
constexpr int S_   = 1024;
constexpr int HID_ = 1024;
constexpr int H_   = 16;
constexpr int D_   = 64;

constexpr int M_ = B_ * S_;    // 4096 GEMM rows
constexpr int N_ = 2 * HID_;   // 2048 (Wq || Wk output dims)
constexpr int K_ = HID_;       // 1024 reduction

// Scratch: projected Q/K in [b, h, s, d] fp32
__device__ float4 g_q4[(size_t)B_ * H_ * S_ * D_ / 4];
__device__ float4 g_k4[(size_t)B_ * H_ * S_ * D_ / 4];
// bf16 hi/lo split operands for the tensor-core projection GEMM
__device__ __nv_bfloat16 g_a_hi[(size_t)M_ * K_];
__device__ __nv_bfloat16 g_a_lo[(size_t)M_ * K_];
__device__ __nv_bfloat16 g_b_hi[(size_t)N_ * K_];
__device__ __nv_bfloat16 g_b_lo[(size_t)N_ * K_];

// ---------------------------------------------------------------------------
// Kernel 0: split fp32 -> bf16 hi/lo for hidden (A) and Wq||Wk (B).
// x = hi + lo with hi = bf16(x), lo = bf16(x - hi). a.b ~= ah.bh + ah.bl + al.bh
// ---------------------------------------------------------------------------
__global__ __launch_bounds__(256) void split_kernel(
    const float* __restrict__ hidden,
    const float* __restrict__ Wq,
    const float* __restrict__ Wk)
{
    const int a4 = M_ * K_ / 4;
    const int w4 = HID_ * K_ / 4;
    int i4 = blockIdx.x * blockDim.x + threadIdx.x;

    const float* src;
    __nv_bfloat16 *hi, *lo;
    size_t off;
    if (i4 < a4)           { src = hidden; off = (size_t)i4 * 4;        hi = g_a_hi; lo = g_a_lo; }
    else if (i4 < a4 + w4) { src = Wq;     off = (size_t)(i4 - a4) * 4; hi = g_b_hi; lo = g_b_lo; }
    else                   { src = Wk;     off = (size_t)(i4 - a4 - w4) * 4;
                             hi = g_b_hi + (size_t)HID_ * K_; lo = g_b_lo + (size_t)HID_ * K_; }

    float4 v = *(const float4*)(src + off);
    __nv_bfloat16 h0 = __float2bfloat16_rn(v.x);
    __nv_bfloat16 h1 = __float2bfloat16_rn(v.y);
    __nv_bfloat16 h2 = __float2bfloat16_rn(v.z);
    __nv_bfloat16 h3 = __float2bfloat16_rn(v.w);
    __nv_bfloat16 l0 = __float2bfloat16_rn(v.x - __bfloat162float(h0));
    __nv_bfloat16 l1 = __float2bfloat16_rn(v.y - __bfloat162float(h1));
    __nv_bfloat16 l2 = __float2bfloat16_rn(v.z - __bfloat162float(h2));
    __nv_bfloat16 l3 = __float2bfloat16_rn(v.w - __bfloat162float(h3));

    ushort4 hv, lv;
    hv.x = *(unsigned short*)&h0; hv.y = *(unsigned short*)&h1;
    hv.z = *(unsigned short*)&h2; hv.w = *(unsigned short*)&h3;
    lv.x = *(unsigned short*)&l0; lv.y = *(unsigned short*)&l1;
    lv.z = *(unsigned short*)&l2; lv.w = *(unsigned short*)&l3;
    *(ushort4*)(hi + off) = hv;
    *(ushort4*)(lo + off) = lv;
}

// ---------------------------------------------------------------------------
// Kernel 1: projection GEMM on WMMA bf16 (hi/lo 3-product, fp32 accum).
//   C[m,n] = sum_k A[m,k] * W[n,k]
// Block tile 64x128, 4 warps, warp tile 32x64 (2x4 fragments of 16x16).
// Output scattered fp32 into g_q4 / g_k4 in [b,h,s,d] layout.
// ---------------------------------------------------------------------------
constexpr int BM = 64;
constexpr int BN = 128;
constexpr int BK = 32;
constexpr int LDP = 40;   // padded smem leading dim (elements)

__global__ __launch_bounds__(128) void proj_mma_kernel()
{
    __shared__ __nv_bfloat16 As[2][BM][LDP];   // [hi/lo][m][k]
    __shared__ __nv_bfloat16 Bs[2][BN][LDP];   // [hi/lo][n][k]

    const int tid = threadIdx.x;
    const int wid = tid >> 5;
    const int wm  = wid & 1;        // warp m index (2)
    const int wn  = wid >> 1;       // warp n index (2)

    const int n0 = blockIdx.x * BN;
    const int m0 = blockIdx.y * BM;

    wmma::fragment<wmma::accumulator, 16, 16, 16, float> c[2][4];
    #pragma unroll
    for (int i = 0; i < 2; i++)
        #pragma unroll
        for (int j = 0; j < 4; j++) wmma::fill_fragment(c[i][j], 0.0f);

    for (int kc = 0; kc < K_; kc += BK) {
        // ---- load A (64x32 hi+lo) and B (128x32 hi+lo) into smem ----
        // A: 64 rows * 4 chunks(16B) = 256 chunks per matrix; 2 per thread.
        #pragma unroll
        for (int p = 0; p < 2; p++) {
            int idx = tid + p * 128;            // 0..255
            int r   = idx >> 2;
            int c8  = (idx & 3) * 8;            // element offset (8 bf16 = 16B)
            size_t go = (size_t)(m0 + r) * K_ + kc + c8;
            *(uint4*)&As[0][r][c8] = *(const uint4*)(g_a_hi + go);
            *(uint4*)&As[1][r][c8] = *(const uint4*)(g_a_lo + go);
        }
        // B: 128 rows * 4 chunks = 512 chunks per matrix; 4 per thread.
        #pragma unroll
        for (int p = 0; p < 4; p++) {
            int idx = tid + p * 128;            // 0..511
            int r   = idx >> 2;
            int c8  = (idx & 3) * 8;
            size_t go = (size_t)(n0 + r) * K_ + kc + c8;
            *(uint4*)&Bs[0][r][c8] = *(const uint4*)(g_b_hi + go);
            *(uint4*)&Bs[1][r][c8] = *(const uint4*)(g_b_lo + go);
        }
        __syncthreads();

        // ---- compute: 2 k-steps of 16 ----
        #pragma unroll
        for (int ks = 0; ks < 2; ks++) {
            wmma::fragment<wmma::matrix_a, 16, 16, 16, __nv_bfloat16, wmma::row_major> ah[2], al[2];
            wmma::fragment<wmma::matrix_b, 16, 16, 16, __nv_bfloat16, wmma::col_major> bh[4], bl[4];
            #pragma unroll
            for (int i = 0; i < 2; i++) {
                wmma::load_matrix_sync(ah[i], &As[0][wm * 32 + i * 16][ks * 16], LDP);
                wmma::load_matrix_sync(al[i], &As[1][wm * 32 + i * 16][ks * 16], LDP);
            }
            #pragma unroll
            for (int j = 0; j < 4; j++) {
                wmma::load_matrix_sync(bh[j], &Bs[0][wn * 64 + j * 16][ks * 16], LDP);
                wmma::load_matrix_sync(bl[j], &Bs[1][wn * 64 + j * 16][ks * 16], LDP);
            }
            #pragma unroll
            for (int i = 0; i < 2; i++)
                #pragma unroll
                for (int j = 0; j < 4; j++) {
                    wmma::mma_sync(c[i][j], ah[i], bh[j], c[i][j]);
                    wmma::mma_sync(c[i][j], ah[i], bl[j], c[i][j]);
                    wmma::mma_sync(c[i][j], al[i], bh[j], c[i][j]);
                }
        }
        __syncthreads();
    }

    // ---- epilogue: store fragments into [b,h,s,d] layout ----
    float* outp   = (n0 < HID_) ? (float*)g_q4 : (float*)g_k4;
    const int nl0 = n0 & (HID_ - 1);

    #pragma unroll
    for (int i = 0; i < 2; i++) {
        const int m = m0 + wm * 32 + i * 16;
        const int b = m >> 10;
        const int s = m & (S_ - 1);
        #pragma unroll
        for (int j = 0; j < 4; j++) {
            const int nl = nl0 + wn * 64 + j * 16;   // 16-wide, within one head
            const int h  = nl >> 6;
            const int d  = nl & 63;
            float* ptr = outp + (((size_t)(b * H_ + h) * S_ + s) * D_ + d);
            wmma::store_matrix_sync(ptr, c[i][j], D_, wmma::mem_row_major);
        }
    }
}

// ---------------------------------------------------------------------------
// Kernel 2: RoPE in place on g_q / g_k.
// ---------------------------------------------------------------------------
__global__ __launch_bounds__(256) void rope_kernel(
    const float* __restrict__ cosp,
    const float* __restrict__ sinp)
{
    int idx = blockIdx.x * blockDim.x + threadIdx.x;
    int d2     = idx & 31;
    int rowidx = idx >> 5;
    int s      = rowidx & (S_ - 1);

    float c  = cosp[s * D_ + d2];
    float sn = sinp[s * D_ + d2];

    float* gq = (float*)g_q4;
    float* gk = (float*)g_k4;
    size_t base = (size_t)rowidx * D_;

    float q1 = gq[base + d2], q2 = gq[base + d2 + 32];
    gq[base + d2]      = fmaf(q1, c, -q2 * sn);
    gq[base + d2 + 32] = fmaf(q2, c,  q1 * sn);

    float k1 = gk[base + d2], k2 = gk[base + d2 + 32];
    gk[base + d2]      = fmaf(k1, c, -k2 * sn);
    gk[base + d2 + 32] = fmaf(k2, c,  k1 * sn);
}

// ---------------------------------------------------------------------------
// Kernel 3: scores GEMM (FFMA), lower-triangular tiles only, raw to d_out.
// ---------------------------------------------------------------------------
__global__ __launch_bounds__(256) void scores_kernel(float* __restrict__ out)
{
    const int bxt = blockIdx.x;
    const int byt = blockIdx.y;
    if (bxt > byt) return;

    const int bh = blockIdx.z;
    const int q0 = byt * 128;
    const int k0 = bxt * 128;
    const float* Qp = (const float*)g_q4 + (size_t)bh * S_ * D_;
    const float* Kp = (const float*)g_k4 + (size_t)bh * S_ * D_;

    __shared__ float Qs[32][128];
    __shared__ float Ks[32][128];

    const int tid = threadIdx.x;
    const int tx  = tid & 15;
    const int ty  = tid >> 4;

    float acc[8][8];
    #pragma unroll
    for (int i = 0; i < 8; i++)
        #pragma unroll
        for (int j = 0; j < 8; j++) acc[i][j] = 0.f;

    for (int c0 = 0; c0 < D_; c0 += 32) {
        #pragma unroll
        for (int p = 0; p < 4; p++) {
            int idx = tid + p * 256;
            int m   = idx >> 3;
            int dq  = (idx & 7) * 4;
            float4 vq = *(const float4*)(Qp + (size_t)(q0 + m) * D_ + c0 + dq);
            Qs[dq + 0][m] = vq.x; Qs[dq + 1][m] = vq.y;
            Qs[dq + 2][m] = vq.z; Qs[dq + 3][m] = vq.w;
            float4 vk = *(const float4*)(Kp + (size_t)(k0 + m) * D_ + c0 + dq);
            Ks[dq + 0][m] = vk.x; Ks[dq + 1][m] = vk.y;
            Ks[dq + 2][m] = vk.z; Ks[dq + 3][m] = vk.w;
        }
        __syncthreads();

        #pragma unroll
        for (int d = 0; d < 32; d++) {
            float a[8], b[8];
            *(float4*)(a)     = *(const float4*)&Qs[d][ty * 8];
            *(float4*)(a + 4) = *(const float4*)&Qs[d][ty * 8 + 4];
            *(float4*)(b)     = *(const float4*)&Ks[d][tx * 8];
            *(float4*)(b + 4) = *(const float4*)&Ks[d][tx * 8 + 4];
            #pragma unroll
            for (int i = 0; i < 8; i++)
                #pragma unroll
                for (int j = 0; j < 8; j++)
                    acc[i][j] = fmaf(a[i], b[j], acc[i][j]);
        }
        __syncthreads();
    }

    #pragma unroll
    for (int i = 0; i < 8; i++) {
        size_t rbase = ((size_t)bh * S_ + (q0 + ty * 8 + i)) * S_ + k0 + tx * 8;
        #pragma unroll
        for (int j4 = 0; j4 < 2; j4++) {
            float4 v = make_float4(acc[i][j4 * 4 + 0] * 0.125f,
                                   acc[i][j4 * 4 + 1] * 0.125f,
                                   acc[i][j4 * 4 + 2] * 0.125f,
                                   acc[i][j4 * 4 + 3] * 0.125f);
            *(float4*)(out + rbase + j4 * 4) = v;
        }
    }
}

// ---------------------------------------------------------------------------
// Kernel 4: causal softmax in place (one block per row).
// ---------------------------------------------------------------------------
__global__ __launch_bounds__(256) void softmax_kernel(float* __restrict__ out)
{
    __shared__ float red[8];

    const int row = blockIdx.x;
    const int qi  = row & (S_ - 1);
    const int nvalid = qi + 1;
    float* rp = out + (size_t)row * S_;

    const int tid  = threadIdx.x;
    const int base = tid * 4;

    float x[4] = {0.f, 0.f, 0.f, 0.f};
    if (base < nvalid) {
        float4 v = *(const float4*)(rp + base);
        x[0] = v.x; x[1] = v.y; x[2] = v.z; x[3] = v.w;
    }

    float mx = -3.402823466e38f;
    #pragma unroll
    for (int c = 0; c < 4; c++)
        if (base + c < nvalid) mx = fmaxf(mx, x[c]);

    #pragma unroll
    for (int o = 16; o > 0; o >>= 1)
        mx = fmaxf(mx, __shfl_xor_sync(0xFFFFFFFFu, mx, o));
    if ((tid & 31) == 0) red[tid >> 5] = mx;
    __syncthreads();

    float allmax = red[0];
    #pragma unroll
    for (int w = 1; w < 8; w++) allmax = fmaxf(allmax, red[w]);
    __syncthreads();

    float e[4];
    float ssum = 0.f;
    #pragma unroll
    for (int c = 0; c < 4; c++) {
        e[c] = (base + c < nvalid) ? __expf(x[c] - allmax) : 0.f;
        ssum += e[c];
    }

    #pragma unroll
    for (int o = 16; o > 0; o >>= 1)
        ssum += __shfl_xor_sync(0xFFFFFFFFu, ssum, o);
    if ((tid & 31) == 0) red[tid >> 5] = ssum;
    __syncthreads();

    float tot = red[0];
    #pragma unroll
    for (int w = 1; w < 8; w++) tot += red[w];
    float inv = 1.0f / tot;

    float4 o4 = make_float4(e[0] * inv, e[1] * inv, e[2] * inv, e[3] * inv);
    *(float4*)(rp + base) = o4;
}

// ---------------------------------------------------------------------------
// Launch
// ---------------------------------------------------------------------------
extern "C" void kernel_launch(void* const* d_in, const int* in_sizes, int n_in,
                              void* d_out, int out_size)
{
    const float* hidden = (const float*)d_in[0];
    const float* cosp   = (const float*)d_in[1];
    const float* sinp   = (const float*)d_in[2];
    const float* Wq     = (const float*)d_in[n_in - 2];
    const float* Wk     = (const float*)d_in[n_in - 1];
    float* out          = (float*)d_out;

    // 0. fp32 -> bf16 hi/lo split of A and W
    int total4 = (M_ * K_ + N_ * K_) / 4;
    split_kernel<<<total4 / 256, 256>>>(hidden, Wq, Wk);

    // 1. Projection GEMM on tensor cores (WMMA bf16, 3-product split)
    dim3 g1(N_ / BN, M_ / BM);
    proj_mma_kernel<<<g1, 128>>>();

    // 2. RoPE in place
    rope_kernel<<<(B_ * H_ * S_ * 32) / 256, 256>>>(cosp, sinp);

    // 3. Scores GEMM (lower-triangular tiles)
    dim3 g2(S_ / 128, S_ / 128, B_ * H_);
    scores_kernel<<<g2, 256>>>(out);

    // 4. Causal softmax in place
    softmax_kernel<<<B_ * H_ * S_, 256>>>(out);
}

// round 5
// speedup vs baseline: 1.8754x; 1.1863x over previous
#include <cuda_runtime.h>
#include <cuda_bf16.h>
#include <mma.h>
#include <cstdint>

using namespace nvcuda;

// Problem constants
constexpr int B_   = 4;
constexpr int S_   = 1024;
constexpr int HID_ = 1024;
constexpr int H_   = 16;
constexpr int D_   = 64;

constexpr int M_ = B_ * S_;    // 4096 GEMM rows
constexpr int N_ = 2 * HID_;   // 2048 (Wq || Wk output dims)
constexpr int K_ = HID_;       // 1024 reduction

// Scratch: projected Q/K in [b, h, s, d] fp32 (pre-RoPE)
__device__ float4 g_q4[(size_t)B_ * H_ * S_ * D_ / 4];
__device__ float4 g_k4[(size_t)B_ * H_ * S_ * D_ / 4];
// bf16 hi/lo split operands for the tensor-core projection GEMM
__device__ __nv_bfloat16 g_a_hi[(size_t)M_ * K_];
__device__ __nv_bfloat16 g_a_lo[(size_t)M_ * K_];
__device__ __nv_bfloat16 g_b_hi[(size_t)N_ * K_];
__device__ __nv_bfloat16 g_b_lo[(size_t)N_ * K_];
// bf16 hi/lo RoPE'd Q/K for the tensor-core scores GEMM, [bh, s, d]
__device__ __nv_bfloat16 g_qh[(size_t)B_ * H_ * S_ * D_];
__device__ __nv_bfloat16 g_ql[(size_t)B_ * H_ * S_ * D_];
__device__ __nv_bfloat16 g_kh[(size_t)B_ * H_ * S_ * D_];
__device__ __nv_bfloat16 g_kl[(size_t)B_ * H_ * S_ * D_];

// ---------------------------------------------------------------------------
// Kernel 0: split fp32 -> bf16 hi/lo for hidden (A) and Wq||Wk (B).
// x = hi + lo with hi = bf16(x), lo = bf16(x - hi). a.b ~= ah.bh + ah.bl + al.bh
// ---------------------------------------------------------------------------
__global__ __launch_bounds__(256) void split_kernel(
    const float* __restrict__ hidden,
    const float* __restrict__ Wq,
    const float* __restrict__ Wk)
{
    const int a4 = M_ * K_ / 4;
    const int w4 = HID_ * K_ / 4;
    int i4 = blockIdx.x * blockDim.x + threadIdx.x;

    const float* src;
    __nv_bfloat16 *hi, *lo;
    size_t off;
    if (i4 < a4)           { src = hidden; off = (size_t)i4 * 4;        hi = g_a_hi; lo = g_a_lo; }
    else if (i4 < a4 + w4) { src = Wq;     off = (size_t)(i4 - a4) * 4; hi = g_b_hi; lo = g_b_lo; }
    else                   { src = Wk;     off = (size_t)(i4 - a4 - w4) * 4;
                             hi = g_b_hi + (size_t)HID_ * K_; lo = g_b_lo + (size_t)HID_ * K_; }

    float4 v = *(const float4*)(src + off);
    __nv_bfloat16 h0 = __float2bfloat16_rn(v.x);
    __nv_bfloat16 h1 = __float2bfloat16_rn(v.y);
    __nv_bfloat16 h2 = __float2bfloat16_rn(v.z);
    __nv_bfloat16 h3 = __float2bfloat16_rn(v.w);
    __nv_bfloat16 l0 = __float2bfloat16_rn(v.x - __bfloat162float(h0));
    __nv_bfloat16 l1 = __float2bfloat16_rn(v.y - __bfloat162float(h1));
    __nv_bfloat16 l2 = __float2bfloat16_rn(v.z - __bfloat162float(h2));
    __nv_bfloat16 l3 = __float2bfloat16_rn(v.w - __bfloat162float(h3));

    ushort4 hv, lv;
    hv.x = *(unsigned short*)&h0; hv.y = *(unsigned short*)&h1;
    hv.z = *(unsigned short*)&h2; hv.w = *(unsigned short*)&h3;
    lv.x = *(unsigned short*)&l0; lv.y = *(unsigned short*)&l1;
    lv.z = *(unsigned short*)&l2; lv.w = *(unsigned short*)&l3;
    *(ushort4*)(hi + off) = hv;
    *(ushort4*)(lo + off) = lv;
}

// ---------------------------------------------------------------------------
// Kernel 1: projection GEMM on WMMA bf16 (hi/lo 3-product, fp32 accum).
// Block tile 64x128, 4 warps, warp tile 32x64 (2x4 fragments of 16x16).
// ---------------------------------------------------------------------------
constexpr int BM = 64;
constexpr int BN = 128;
constexpr int BK = 32;
constexpr int LDP = 40;   // padded smem leading dim (elements)

__global__ __launch_bounds__(128) void proj_mma_kernel()
{
    __shared__ __nv_bfloat16 As[2][BM][LDP];   // [hi/lo][m][k]
    __shared__ __nv_bfloat16 Bs[2][BN][LDP];   // [hi/lo][n][k]

    const int tid = threadIdx.x;
    const int wid = tid >> 5;
    const int wm  = wid & 1;
    const int wn  = wid >> 1;

    const int n0 = blockIdx.x * BN;
    const int m0 = blockIdx.y * BM;

    wmma::fragment<wmma::accumulator, 16, 16, 16, float> c[2][4];
    #pragma unroll
    for (int i = 0; i < 2; i++)
        #pragma unroll
        for (int j = 0; j < 4; j++) wmma::fill_fragment(c[i][j], 0.0f);

    for (int kc = 0; kc < K_; kc += BK) {
        #pragma unroll
        for (int p = 0; p < 2; p++) {
            int idx = tid + p * 128;
            int r   = idx >> 2;
            int c8  = (idx & 3) * 8;
            size_t go = (size_t)(m0 + r) * K_ + kc + c8;
            *(uint4*)&As[0][r][c8] = *(const uint4*)(g_a_hi + go);
            *(uint4*)&As[1][r][c8] = *(const uint4*)(g_a_lo + go);
        }
        #pragma unroll
        for (int p = 0; p < 4; p++) {
            int idx = tid + p * 128;
            int r   = idx >> 2;
            int c8  = (idx & 3) * 8;
            size_t go = (size_t)(n0 + r) * K_ + kc + c8;
            *(uint4*)&Bs[0][r][c8] = *(const uint4*)(g_b_hi + go);
            *(uint4*)&Bs[1][r][c8] = *(const uint4*)(g_b_lo + go);
        }
        __syncthreads();

        #pragma unroll
        for (int ks = 0; ks < 2; ks++) {
            wmma::fragment<wmma::matrix_a, 16, 16, 16, __nv_bfloat16, wmma::row_major> ah[2], al[2];
            wmma::fragment<wmma::matrix_b, 16, 16, 16, __nv_bfloat16, wmma::col_major> bh[4], bl[4];
            #pragma unroll
            for (int i = 0; i < 2; i++) {
                wmma::load_matrix_sync(ah[i], &As[0][wm * 32 + i * 16][ks * 16], LDP);
                wmma::load_matrix_sync(al[i], &As[1][wm * 32 + i * 16][ks * 16], LDP);
            }
            #pragma unroll
            for (int j = 0; j < 4; j++) {
                wmma::load_matrix_sync(bh[j], &Bs[0][wn * 64 + j * 16][ks * 16], LDP);
                wmma::load_matrix_sync(bl[j], &Bs[1][wn * 64 + j * 16][ks * 16], LDP);
            }
            #pragma unroll
            for (int i = 0; i < 2; i++)
                #pragma unroll
                for (int j = 0; j < 4; j++) {
                    wmma::mma_sync(c[i][j], ah[i], bh[j], c[i][j]);
                    wmma::mma_sync(c[i][j], ah[i], bl[j], c[i][j]);
                    wmma::mma_sync(c[i][j], al[i], bh[j], c[i][j]);
                }
        }
        __syncthreads();
    }

    float* outp   = (n0 < HID_) ? (float*)g_q4 : (float*)g_k4;
    const int nl0 = n0 & (HID_ - 1);

    #pragma unroll
    for (int i = 0; i < 2; i++) {
        const int m = m0 + wm * 32 + i * 16;
        const int b = m >> 10;
        const int s = m & (S_ - 1);
        #pragma unroll
        for (int j = 0; j < 4; j++) {
            const int nl = nl0 + wn * 64 + j * 16;
            const int h  = nl >> 6;
            const int d  = nl & 63;
            float* ptr = outp + (((size_t)(b * H_ + h) * S_ + s) * D_ + d);
            wmma::store_matrix_sync(ptr, c[i][j], D_, wmma::mem_row_major);
        }
    }
}

// ---------------------------------------------------------------------------
// Kernel 2: RoPE + bf16 hi/lo split.
// Reads fp32 g_q4/g_k4, rotates, writes hi/lo bf16 into g_qh/g_ql/g_kh/g_kl.
// ---------------------------------------------------------------------------
__device__ __forceinline__ void split_store(__nv_bfloat16* hi, __nv_bfloat16* lo,
                                            size_t idx, float v) {
    __nv_bfloat16 h = __float2bfloat16_rn(v);
    __nv_bfloat16 l = __float2bfloat16_rn(v - __bfloat162float(h));
    hi[idx] = h; lo[idx] = l;
}

__global__ __launch_bounds__(256) void rope_split_kernel(
    const float* __restrict__ cosp,
    const float* __restrict__ sinp)
{
    int idx = blockIdx.x * blockDim.x + threadIdx.x;
    int d2     = idx & 31;
    int rowidx = idx >> 5;              // (b*H + h)*S + s
    int s      = rowidx & (S_ - 1);

    float c  = cosp[s * D_ + d2];
    float sn = sinp[s * D_ + d2];

    const float* gq = (const float*)g_q4;
    const float* gk = (const float*)g_k4;
    size_t base = (size_t)rowidx * D_;

    float q1 = gq[base + d2], q2 = gq[base + d2 + 32];
    float qr1 = fmaf(q1, c, -q2 * sn);
    float qr2 = fmaf(q2, c,  q1 * sn);
    split_store(g_qh, g_ql, base + d2,      qr1);
    split_store(g_qh, g_ql, base + d2 + 32, qr2);

    float k1 = gk[base + d2], k2 = gk[base + d2 + 32];
    float kr1 = fmaf(k1, c, -k2 * sn);
    float kr2 = fmaf(k2, c,  k1 * sn);
    split_store(g_kh, g_kl, base + d2,      kr1);
    split_store(g_kh, g_kl, base + d2 + 32, kr2);
}

// ---------------------------------------------------------------------------
// Kernel 3: scores GEMM on WMMA bf16 (hi/lo 3-product, fp32 accum).
//   scores[bh, q, k] = (Q[q,:] . K[k,:]) / 8, lower-triangular tiles only.
// Tile 128(q) x 128(k), K-dim = 64 loaded once. 8 warps, warp tile 32x64.
// ---------------------------------------------------------------------------
constexpr int SLDP     = 72;                                 // padded ld (64+8)
constexpr int S_TILE_E = 2 * 128 * SLDP;                     // elems per matrix (hi+lo)
constexpr int S_SMEM_B = 2 * S_TILE_E * (int)sizeof(__nv_bfloat16);  // 73728 B

__global__ __launch_bounds__(256) void scores_mma_kernel(float* __restrict__ out)
{
    const int bxt = blockIdx.x;   // k tile
    const int byt = blockIdx.y;   // q tile
    if (bxt > byt) return;        // fully masked -> skip

    extern __shared__ __nv_bfloat16 smem[];
    __nv_bfloat16 (*Qs)[128][SLDP] = (__nv_bfloat16 (*)[128][SLDP])smem;
    __nv_bfloat16 (*Ks)[128][SLDP] = (__nv_bfloat16 (*)[128][SLDP])(smem + S_TILE_E);

    const int bh = blockIdx.z;
    const int q0 = byt * 128;
    const int k0 = bxt * 128;
    const size_t qbase = (size_t)bh * S_ * D_ + (size_t)q0 * D_;
    const size_t kbase = (size_t)bh * S_ * D_ + (size_t)k0 * D_;

    const int tid = threadIdx.x;
    const int wid = tid >> 5;
    const int wm  = wid & 3;       // 4 warps over q (32 rows each)
    const int wn  = wid >> 2;      // 2 warps over k (64 cols each)

    // ---- load Q and K tiles (hi+lo): per matrix 2*128 rows * 8 chunks(16B) = 2048 ----
    #pragma unroll
    for (int p = 0; p < 8; p++) {
        int idx = tid + p * 256;          // 0..2047
        int hl  = idx >> 10;              // 0 = hi, 1 = lo
        int i2  = idx & 1023;
        int r   = i2 >> 3;                // 0..127
        int c8  = (i2 & 7) * 8;           // 0..56
        const __nv_bfloat16* src = hl ? g_ql : g_qh;
        *(uint4*)&Qs[hl][r][c8] = *(const uint4*)(src + qbase + (size_t)r * D_ + c8);
    }
    #pragma unroll
    for (int p = 0; p < 8; p++) {
        int idx = tid + p * 256;
        int hl  = idx >> 10;
        int i2  = idx & 1023;
        int r   = i2 >> 3;
        int c8  = (i2 & 7) * 8;
        const __nv_bfloat16* src = hl ? g_kl : g_kh;
        *(uint4*)&Ks[hl][r][c8] = *(const uint4*)(src + kbase + (size_t)r * D_ + c8);
    }
    __syncthreads();

    wmma::fragment<wmma::accumulator, 16, 16, 16, float> c[2][4];
    #pragma unroll
    for (int i = 0; i < 2; i++)
        #pragma unroll
        for (int j = 0; j < 4; j++) wmma::fill_fragment(c[i][j], 0.0f);

    #pragma unroll
    for (int ks = 0; ks < 4; ks++) {      // 4 k-steps of 16 over D=64
        wmma::fragment<wmma::matrix_a, 16, 16, 16, __nv_bfloat16, wmma::row_major> ah[2], al[2];
        wmma::fragment<wmma::matrix_b, 16, 16, 16, __nv_bfloat16, wmma::col_major> bh[4], bl[4];
        #pragma unroll
        for (int i = 0; i < 2; i++) {
            wmma::load_matrix_sync(ah[i], &Qs[0][wm * 32 + i * 16][ks * 16], SLDP);
            wmma::load_matrix_sync(al[i], &Qs[1][wm * 32 + i * 16][ks * 16], SLDP);
        }
        #pragma unroll
        for (int j = 0; j < 4; j++) {
            wmma::load_matrix_sync(bh[j], &Ks[0][wn * 64 + j * 16][ks * 16], SLDP);
            wmma::load_matrix_sync(bl[j], &Ks[1][wn * 64 + j * 16][ks * 16], SLDP);
        }
        #pragma unroll
        for (int i = 0; i < 2; i++)
            #pragma unroll
            for (int j = 0; j < 4; j++) {
                wmma::mma_sync(c[i][j], ah[i], bh[j], c[i][j]);
                wmma::mma_sync(c[i][j], ah[i], bl[j], c[i][j]);
                wmma::mma_sync(c[i][j], al[i], bh[j], c[i][j]);
            }
    }

    // ---- epilogue: scale by 1/8 and store raw scores ----
    #pragma unroll
    for (int i = 0; i < 2; i++) {
        const int q = q0 + wm * 32 + i * 16;
        #pragma unroll
        for (int j = 0; j < 4; j++) {
            const int kcol = k0 + wn * 64 + j * 16;
            #pragma unroll
            for (int e = 0; e < c[i][j].num_elements; e++)
                c[i][j].x[e] *= 0.125f;
            float* ptr = out + ((size_t)bh * S_ + q) * S_ + kcol;
            wmma::store_matrix_sync(ptr, c[i][j], S_, wmma::mem_row_major);
        }
    }
}

// ---------------------------------------------------------------------------
// Kernel 4: causal softmax in place (one block per row).
// ---------------------------------------------------------------------------
__global__ __launch_bounds__(256) void softmax_kernel(float* __restrict__ out)
{
    __shared__ float red[8];

    const int row = blockIdx.x;
    const int qi  = row & (S_ - 1);
    const int nvalid = qi + 1;
    float* rp = out + (size_t)row * S_;

    const int tid  = threadIdx.x;
    const int base = tid * 4;

    float x[4] = {0.f, 0.f, 0.f, 0.f};
    if (base < nvalid) {
        float4 v = *(const float4*)(rp + base);
        x[0] = v.x; x[1] = v.y; x[2] = v.z; x[3] = v.w;
    }

    float mx = -3.402823466e38f;
    #pragma unroll
    for (int c = 0; c < 4; c++)
        if (base + c < nvalid) mx = fmaxf(mx, x[c]);

    #pragma unroll
    for (int o = 16; o > 0; o >>= 1)
        mx = fmaxf(mx, __shfl_xor_sync(0xFFFFFFFFu, mx, o));
    if ((tid & 31) == 0) red[tid >> 5] = mx;
    __syncthreads();

    float allmax = red[0];
    #pragma unroll
    for (int w = 1; w < 8; w++) allmax = fmaxf(allmax, red[w]);
    __syncthreads();

    float e[4];
    float ssum = 0.f;
    #pragma unroll
    for (int c = 0; c < 4; c++) {
        e[c] = (base + c < nvalid) ? __expf(x[c] - allmax) : 0.f;
        ssum += e[c];
    }

    #pragma unroll
    for (int o = 16; o > 0; o >>= 1)
        ssum += __shfl_xor_sync(0xFFFFFFFFu, ssum, o);
    if ((tid & 31) == 0) red[tid >> 5] = ssum;
    __syncthreads();

    float tot = red[0];
    #pragma unroll
    for (int w = 1; w < 8; w++) tot += red[w];
    float inv = 1.0f / tot;

    float4 o4 = make_float4(e[0] * inv, e[1] * inv, e[2] * inv, e[3] * inv);
    *(float4*)(rp + base) = o4;
}

// ---------------------------------------------------------------------------
// Launch
// ---------------------------------------------------------------------------
extern "C" void kernel_launch(void* const* d_in, const int* in_sizes, int n_in,
                              void* d_out, int out_size)
{
    const float* hidden = (const float*)d_in[0];
    const float* cosp   = (const float*)d_in[1];
    const float* sinp   = (const float*)d_in[2];
    const float* Wq     = (const float*)d_in[n_in - 2];
    const float* Wk     = (const float*)d_in[n_in - 1];
    float* out          = (float*)d_out;

    // Idempotent, no static state (harness forbids static guards).
    cudaFuncSetAttribute(scores_mma_kernel,
                         cudaFuncAttributeMaxDynamicSharedMemorySize, S_SMEM_B);

    // 0. fp32 -> bf16 hi/lo split of A and W
    int total4 = (M_ * K_ + N_ * K_) / 4;
    split_kernel<<<total4 / 256, 256>>>(hidden, Wq, Wk);

    // 1. Projection GEMM on tensor cores (WMMA bf16, 3-product split)
    dim3 g1(N_ / BN, M_ / BM);
    proj_mma_kernel<<<g1, 128>>>();

    // 2. RoPE + hi/lo split for scores operands
    rope_split_kernel<<<(B_ * H_ * S_ * 32) / 256, 256>>>(cosp, sinp);

    // 3. Scores GEMM on tensor cores (lower-triangular tiles)
    dim3 g2(S_ / 128, S_ / 128, B_ * H_);
    scores_mma_kernel<<<g2, 256, S_SMEM_B>>>(out);

    // 4. Causal softmax in place
    softmax_kernel<<<B_ * H_ * S_, 256>>>(out);
}

// round 6
// speedup vs baseline: 2.0040x; 1.0686x over previous
#include <cuda_runtime.h>
#include <cuda_bf16.h>
#include <mma.h>
#include <cstdint>

using namespace nvcuda;

// Problem constants
constexpr int B_   = 4;
constexpr int S_   = 1024;
constexpr int HID_ = 1024;
constexpr int H_   = 16;
constexpr int D_   = 64;

constexpr int M_ = B_ * S_;    // 4096 GEMM rows
constexpr int N_ = 2 * HID_;   // 2048 (Wq || Wk output dims)
constexpr int K_ = HID_;       // 1024 reduction

// Scratch: projected Q/K in [b, h, s, d] fp32 (pre-RoPE)
__device__ float4 g_q4[(size_t)B_ * H_ * S_ * D_ / 4];
__device__ float4 g_k4[(size_t)B_ * H_ * S_ * D_ / 4];
// bf16 hi/lo split operands for the tensor-core projection GEMM
__device__ __nv_bfloat16 g_a_hi[(size_t)M_ * K_];
__device__ __nv_bfloat16 g_a_lo[(size_t)M_ * K_];
__device__ __nv_bfloat16 g_b_hi[(size_t)N_ * K_];
__device__ __nv_bfloat16 g_b_lo[(size_t)N_ * K_];
// bf16 hi/lo RoPE'd Q/K for the tensor-core scores GEMM, [bh, s, d]
__device__ __nv_bfloat16 g_qh[(size_t)B_ * H_ * S_ * D_];
__device__ __nv_bfloat16 g_ql[(size_t)B_ * H_ * S_ * D_];
__device__ __nv_bfloat16 g_kh[(size_t)B_ * H_ * S_ * D_];
__device__ __nv_bfloat16 g_kl[(size_t)B_ * H_ * S_ * D_];

// ---------------------------------------------------------------------------
// cp.async helpers (baseline ISA, sm_80+)
// ---------------------------------------------------------------------------
__device__ __forceinline__ uint32_t smem_u32(const void* p) {
    uint32_t a;
    asm("{ .reg .u64 t; cvta.to.shared.u64 t, %1; cvt.u32.u64 %0, t; }"
        : "=r"(a) : "l"(p));
    return a;
}
__device__ __forceinline__ void cp_async16(uint32_t dst, const void* src) {
    asm volatile("cp.async.cg.shared.global [%0], [%1], 16;"
                 :: "r"(dst), "l"(src) : "memory");
}
__device__ __forceinline__ void cp_commit() {
    asm volatile("cp.async.commit_group;" ::: "memory");
}
template<int N>
__device__ __forceinline__ void cp_wait() {
    asm volatile("cp.async.wait_group %0;" :: "n"(N) : "memory");
}

// ---------------------------------------------------------------------------
// Kernel 0: split fp32 -> bf16 hi/lo for hidden (A) and Wq||Wk (B).
// x = hi + lo with hi = bf16(x), lo = bf16(x - hi). a.b ~= ah.bh + ah.bl + al.bh
// ---------------------------------------------------------------------------
__global__ __launch_bounds__(256) void split_kernel(
    const float* __restrict__ hidden,
    const float* __restrict__ Wq,
    const float* __restrict__ Wk)
{
    const int a4 = M_ * K_ / 4;
    const int w4 = HID_ * K_ / 4;
    int i4 = blockIdx.x * blockDim.x + threadIdx.x;

    const float* src;
    __nv_bfloat16 *hi, *lo;
    size_t off;
    if (i4 < a4)           { src = hidden; off = (size_t)i4 * 4;        hi = g_a_hi; lo = g_a_lo; }
    else if (i4 < a4 + w4) { src = Wq;     off = (size_t)(i4 - a4) * 4; hi = g_b_hi; lo = g_b_lo; }
    else                   { src = Wk;     off = (size_t)(i4 - a4 - w4) * 4;
                             hi = g_b_hi + (size_t)HID_ * K_; lo = g_b_lo + (size_t)HID_ * K_; }

    float4 v = *(const float4*)(src + off);
    __nv_bfloat16 h0 = __float2bfloat16_rn(v.x);
    __nv_bfloat16 h1 = __float2bfloat16_rn(v.y);
    __nv_bfloat16 h2 = __float2bfloat16_rn(v.z);
    __nv_bfloat16 h3 = __float2bfloat16_rn(v.w);
    __nv_bfloat16 l0 = __float2bfloat16_rn(v.x - __bfloat162float(h0));
    __nv_bfloat16 l1 = __float2bfloat16_rn(v.y - __bfloat162float(h1));
    __nv_bfloat16 l2 = __float2bfloat16_rn(v.z - __bfloat162float(h2));
    __nv_bfloat16 l3 = __float2bfloat16_rn(v.w - __bfloat162float(h3));

    ushort4 hv, lv;
    hv.x = *(unsigned short*)&h0; hv.y = *(unsigned short*)&h1;
    hv.z = *(unsigned short*)&h2; hv.w = *(unsigned short*)&h3;
    lv.x = *(unsigned short*)&l0; lv.y = *(unsigned short*)&l1;
    lv.z = *(unsigned short*)&l2; lv.w = *(unsigned short*)&l3;
    *(ushort4*)(hi + off) = hv;
    *(ushort4*)(lo + off) = lv;
}

// ---------------------------------------------------------------------------
// Kernel 1: projection GEMM on WMMA bf16 (hi/lo 3-product, fp32 accum).
// Block tile 64x128, 4 warps, warp tile 32x64. 2-stage cp.async pipeline.
// ---------------------------------------------------------------------------
constexpr int BM  = 64;
constexpr int BN  = 128;
constexpr int BK  = 32;
constexpr int LDP = 40;   // padded smem leading dim (elements); 40*2B=80B, 16B-aligned rows

// dynamic smem layout (elements): As[st][hl][BM][LDP] then Bs[st][hl][BN][LDP]
constexpr int AS_E     = 2 * 2 * BM * LDP;         // 10240
constexpr int BS_E     = 2 * 2 * BN * LDP;         // 20480
constexpr int P_SMEM_B = (AS_E + BS_E) * 2;        // 61440 bytes

__device__ __forceinline__ int as_off(int st, int hl, int r, int cc) {
    return ((st * 2 + hl) * BM + r) * LDP + cc;
}
__device__ __forceinline__ int bs_off(int st, int hl, int r, int cc) {
    return AS_E + ((st * 2 + hl) * BN + r) * LDP + cc;
}

__global__ __launch_bounds__(128) void proj_mma_kernel()
{
    extern __shared__ __nv_bfloat16 psm[];

    const int tid = threadIdx.x;
    const int wid = tid >> 5;
    const int wm  = wid & 1;
    const int wn  = wid >> 1;

    const int n0 = blockIdx.x * BN;
    const int m0 = blockIdx.y * BM;

    // async load of one K-chunk into stage st
    auto load_stage = [&](int st, int kc) {
        // A: 2(hi/lo) x 64 rows x 4 chunks(16B) = 512 -> 4 per thread
        #pragma unroll
        for (int p = 0; p < 4; p++) {
            int idx = tid + p * 128;
            int hl  = idx >> 8;
            int i2  = idx & 255;
            int r   = i2 >> 2;
            int c8  = (i2 & 3) * 8;
            const __nv_bfloat16* src = hl ? g_a_lo : g_a_hi;
            cp_async16(smem_u32(&psm[as_off(st, hl, r, c8)]),
                       src + (size_t)(m0 + r) * K_ + kc + c8);
        }
        // B: 2 x 128 rows x 4 chunks = 1024 -> 8 per thread
        #pragma unroll
        for (int p = 0; p < 8; p++) {
            int idx = tid + p * 128;
            int hl  = idx >> 9;
            int i2  = idx & 511;
            int r   = i2 >> 2;
            int c8  = (i2 & 3) * 8;
            const __nv_bfloat16* src = hl ? g_b_lo : g_b_hi;
            cp_async16(smem_u32(&psm[bs_off(st, hl, r, c8)]),
                       src + (size_t)(n0 + r) * K_ + kc + c8);
        }
    };

    wmma::fragment<wmma::accumulator, 16, 16, 16, float> c[2][4];
    #pragma unroll
    for (int i = 0; i < 2; i++)
        #pragma unroll
        for (int j = 0; j < 4; j++) wmma::fill_fragment(c[i][j], 0.0f);

    constexpr int NCH = K_ / BK;   // 32
    load_stage(0, 0);
    cp_commit();

    for (int ch = 0; ch < NCH; ch++) {
        const int st = ch & 1;
        if (ch + 1 < NCH) {
            load_stage(st ^ 1, (ch + 1) * BK);
            cp_commit();
            cp_wait<1>();
        } else {
            cp_wait<0>();
        }
        __syncthreads();

        #pragma unroll
        for (int ks = 0; ks < 2; ks++) {
            wmma::fragment<wmma::matrix_a, 16, 16, 16, __nv_bfloat16, wmma::row_major> ah[2], al[2];
            #pragma unroll
            for (int i = 0; i < 2; i++) {
                wmma::load_matrix_sync(ah[i], &psm[as_off(st, 0, wm * 32 + i * 16, ks * 16)], LDP);
                wmma::load_matrix_sync(al[i], &psm[as_off(st, 1, wm * 32 + i * 16, ks * 16)], LDP);
            }
            #pragma unroll
            for (int j = 0; j < 4; j++) {
                wmma::fragment<wmma::matrix_b, 16, 16, 16, __nv_bfloat16, wmma::col_major> bh, bl;
                wmma::load_matrix_sync(bh, &psm[bs_off(st, 0, wn * 64 + j * 16, ks * 16)], LDP);
                wmma::load_matrix_sync(bl, &psm[bs_off(st, 1, wn * 64 + j * 16, ks * 16)], LDP);
                #pragma unroll
                for (int i = 0; i < 2; i++) {
                    wmma::mma_sync(c[i][j], ah[i], bh, c[i][j]);
                    wmma::mma_sync(c[i][j], ah[i], bl, c[i][j]);
                    wmma::mma_sync(c[i][j], al[i], bh, c[i][j]);
                }
            }
        }
        __syncthreads();
    }

    float* outp   = (n0 < HID_) ? (float*)g_q4 : (float*)g_k4;
    const int nl0 = n0 & (HID_ - 1);

    #pragma unroll
    for (int i = 0; i < 2; i++) {
        const int m = m0 + wm * 32 + i * 16;
        const int b = m >> 10;
        const int s = m & (S_ - 1);
        #pragma unroll
        for (int j = 0; j < 4; j++) {
            const int nl = nl0 + wn * 64 + j * 16;
            const int h  = nl >> 6;
            const int d  = nl & 63;
            float* ptr = outp + (((size_t)(b * H_ + h) * S_ + s) * D_ + d);
            wmma::store_matrix_sync(ptr, c[i][j], D_, wmma::mem_row_major);
        }
    }
}

// ---------------------------------------------------------------------------
// Kernel 2: RoPE + bf16 hi/lo split.
// ---------------------------------------------------------------------------
__device__ __forceinline__ void split_store(__nv_bfloat16* hi, __nv_bfloat16* lo,
                                            size_t idx, float v) {
    __nv_bfloat16 h = __float2bfloat16_rn(v);
    __nv_bfloat16 l = __float2bfloat16_rn(v - __bfloat162float(h));
    hi[idx] = h; lo[idx] = l;
}

__global__ __launch_bounds__(256) void rope_split_kernel(
    const float* __restrict__ cosp,
    const float* __restrict__ sinp)
{
    int idx = blockIdx.x * blockDim.x + threadIdx.x;
    int d2     = idx & 31;
    int rowidx = idx >> 5;              // (b*H + h)*S + s
    int s      = rowidx & (S_ - 1);

    float c  = cosp[s * D_ + d2];
    float sn = sinp[s * D_ + d2];

    const float* gq = (const float*)g_q4;
    const float* gk = (const float*)g_k4;
    size_t base = (size_t)rowidx * D_;

    float q1 = gq[base + d2], q2 = gq[base + d2 + 32];
    float qr1 = fmaf(q1, c, -q2 * sn);
    float qr2 = fmaf(q2, c,  q1 * sn);
    split_store(g_qh, g_ql, base + d2,      qr1);
    split_store(g_qh, g_ql, base + d2 + 32, qr2);

    float k1 = gk[base + d2], k2 = gk[base + d2 + 32];
    float kr1 = fmaf(k1, c, -k2 * sn);
    float kr2 = fmaf(k2, c,  k1 * sn);
    split_store(g_kh, g_kl, base + d2,      kr1);
    split_store(g_kh, g_kl, base + d2 + 32, kr2);
}

// ---------------------------------------------------------------------------
// Kernel 3: scores GEMM on WMMA bf16 (hi/lo 3-product, fp32 accum).
// Tile 128(q) x 128(k), D=64 loaded once. 8 warps, warp tile 32x64.
// __launch_bounds__(256,2) forces <=128 regs -> 2 CTAs/SM.
// ---------------------------------------------------------------------------
constexpr int SLDP     = 72;                                 // padded ld (64+8)
constexpr int S_TILE_E = 2 * 128 * SLDP;                     // elems per matrix (hi+lo)
constexpr int S_SMEM_B = 2 * S_TILE_E * (int)sizeof(__nv_bfloat16);  // 73728 B

__global__ __launch_bounds__(256, 2) void scores_mma_kernel(float* __restrict__ out)
{
    const int bxt = blockIdx.x;   // k tile
    const int byt = blockIdx.y;   // q tile
    if (bxt > byt) return;        // fully masked -> skip

    extern __shared__ __nv_bfloat16 smem[];
    __nv_bfloat16 (*Qs)[128][SLDP] = (__nv_bfloat16 (*)[128][SLDP])smem;
    __nv_bfloat16 (*Ks)[128][SLDP] = (__nv_bfloat16 (*)[128][SLDP])(smem + S_TILE_E);

    const int bh = blockIdx.z;
    const int q0 = byt * 128;
    const int k0 = bxt * 128;
    const size_t qbase = (size_t)bh * S_ * D_ + (size_t)q0 * D_;
    const size_t kbase = (size_t)bh * S_ * D_ + (size_t)k0 * D_;

    const int tid = threadIdx.x;
    const int wid = tid >> 5;
    const int wm  = wid & 3;       // 4 warps over q (32 rows each)
    const int wn  = wid >> 2;      // 2 warps over k (64 cols each)

    // ---- load Q and K tiles (hi+lo): per matrix 2*128 rows * 8 chunks(16B) = 2048 ----
    #pragma unroll
    for (int p = 0; p < 8; p++) {
        int idx = tid + p * 256;          // 0..2047
        int hl  = idx >> 10;
        int i2  = idx & 1023;
        int r   = i2 >> 3;
        int c8  = (i2 & 7) * 8;
        const __nv_bfloat16* src = hl ? g_ql : g_qh;
        *(uint4*)&Qs[hl][r][c8] = *(const uint4*)(src + qbase + (size_t)r * D_ + c8);
    }
    #pragma unroll
    for (int p = 0; p < 8; p++) {
        int idx = tid + p * 256;
        int hl  = idx >> 10;
        int i2  = idx & 1023;
        int r   = i2 >> 3;
        int c8  = (i2 & 7) * 8;
        const __nv_bfloat16* src = hl ? g_kl : g_kh;
        *(uint4*)&Ks[hl][r][c8] = *(const uint4*)(src + kbase + (size_t)r * D_ + c8);
    }
    __syncthreads();

    wmma::fragment<wmma::accumulator, 16, 16, 16, float> c[2][4];
    #pragma unroll
    for (int i = 0; i < 2; i++)
        #pragma unroll
        for (int j = 0; j < 4; j++) wmma::fill_fragment(c[i][j], 0.0f);

    #pragma unroll
    for (int ks = 0; ks < 4; ks++) {      // 4 k-steps of 16 over D=64
        wmma::fragment<wmma::matrix_a, 16, 16, 16, __nv_bfloat16, wmma::row_major> ah[2], al[2];
        #pragma unroll
        for (int i = 0; i < 2; i++) {
            wmma::load_matrix_sync(ah[i], &Qs[0][wm * 32 + i * 16][ks * 16], SLDP);
            wmma::load_matrix_sync(al[i], &Qs[1][wm * 32 + i * 16][ks * 16], SLDP);
        }
        #pragma unroll
        for (int j = 0; j < 4; j++) {
            wmma::fragment<wmma::matrix_b, 16, 16, 16, __nv_bfloat16, wmma::col_major> bh, bl;
            wmma::load_matrix_sync(bh, &Ks[0][wn * 64 + j * 16][ks * 16], SLDP);
            wmma::load_matrix_sync(bl, &Ks[1][wn * 64 + j * 16][ks * 16], SLDP);
            #pragma unroll
            for (int i = 0; i < 2; i++) {
                wmma::mma_sync(c[i][j], ah[i], bh, c[i][j]);
                wmma::mma_sync(c[i][j], ah[i], bl, c[i][j]);
                wmma::mma_sync(c[i][j], al[i], bh, c[i][j]);
            }
        }
    }

    // ---- epilogue: scale by 1/8 and store raw scores ----
    #pragma unroll
    for (int i = 0; i < 2; i++) {
        const int q = q0 + wm * 32 + i * 16;
        #pragma unroll
        for (int j = 0; j < 4; j++) {
            const int kcol = k0 + wn * 64 + j * 16;
            #pragma unroll
            for (int e = 0; e < c[i][j].num_elements; e++)
                c[i][j].x[e] *= 0.125f;
            float* ptr = out + ((size_t)bh * S_ + q) * S_ + kcol;
            wmma::store_matrix_sync(ptr, c[i][j], S_, wmma::mem_row_major);
        }
    }
}

// ---------------------------------------------------------------------------
// Kernel 4: causal softmax in place (one block per row).
// ---------------------------------------------------------------------------
__global__ __launch_bounds__(256) void softmax_kernel(float* __restrict__ out)
{
    __shared__ float red[8];

    const int row = blockIdx.x;
    const int qi  = row & (S_ - 1);
    const int nvalid = qi + 1;
    float* rp = out + (size_t)row * S_;

    const int tid  = threadIdx.x;
    const int base = tid * 4;

    float x[4] = {0.f, 0.f, 0.f, 0.f};
    if (base < nvalid) {
        float4 v = *(const float4*)(rp + base);
        x[0] = v.x; x[1] = v.y; x[2] = v.z; x[3] = v.w;
    }

    float mx = -3.402823466e38f;
    #pragma unroll
    for (int c = 0; c < 4; c++)
        if (base + c < nvalid) mx = fmaxf(mx, x[c]);

    #pragma unroll
    for (int o = 16; o > 0; o >>= 1)
        mx = fmaxf(mx, __shfl_xor_sync(0xFFFFFFFFu, mx, o));
    if ((tid & 31) == 0) red[tid >> 5] = mx;
    __syncthreads();

    float allmax = red[0];
    #pragma unroll
    for (int w = 1; w < 8; w++) allmax = fmaxf(allmax, red[w]);
    __syncthreads();

    float e[4];
    float ssum = 0.f;
    #pragma unroll
    for (int c = 0; c < 4; c++) {
        e[c] = (base + c < nvalid) ? __expf(x[c] - allmax) : 0.f;
        ssum += e[c];
    }

    #pragma unroll
    for (int o = 16; o > 0; o >>= 1)
        ssum += __shfl_xor_sync(0xFFFFFFFFu, ssum, o);
    if ((tid & 31) == 0) red[tid >> 5] = ssum;
    __syncthreads();

    float tot = red[0];
    #pragma unroll
    for (int w = 1; w < 8; w++) tot += red[w];
    float inv = 1.0f / tot;

    float4 o4 = make_float4(e[0] * inv, e[1] * inv, e[2] * inv, e[3] * inv);
    *(float4*)(rp + base) = o4;
}

// ---------------------------------------------------------------------------
// Launch
// ---------------------------------------------------------------------------
extern "C" void kernel_launch(void* const* d_in, const int* in_sizes, int n_in,
                              void* d_out, int out_size)
{
    const float* hidden = (const float*)d_in[0];
    const float* cosp   = (const float*)d_in[1];
    const float* sinp   = (const float*)d_in[2];
    const float* Wq     = (const float*)d_in[n_in - 2];
    const float* Wk     = (const float*)d_in[n_in - 1];
    float* out          = (float*)d_out;

    // Idempotent attribute setters (no static guards per harness rules).
    cudaFuncSetAttribute(proj_mma_kernel,
                         cudaFuncAttributeMaxDynamicSharedMemorySize, P_SMEM_B);
    cudaFuncSetAttribute(scores_mma_kernel,
                         cudaFuncAttributeMaxDynamicSharedMemorySize, S_SMEM_B);

    // 0. fp32 -> bf16 hi/lo split of A and W
    int total4 = (M_ * K_ + N_ * K_) / 4;
    split_kernel<<<total4 / 256, 256>>>(hidden, Wq, Wk);

    // 1. Projection GEMM on tensor cores (WMMA bf16, 3-product split, cp.async)
    dim3 g1(N_ / BN, M_ / BM);
    proj_mma_kernel<<<g1, 128, P_SMEM_B>>>();

    // 2. RoPE + hi/lo split for scores operands
    rope_split_kernel<<<(B_ * H_ * S_ * 32) / 256, 256>>>(cosp, sinp);

    // 3. Scores GEMM on tensor cores (lower-triangular tiles)
    dim3 g2(S_ / 128, S_ / 128, B_ * H_);
    scores_mma_kernel<<<g2, 256, S_SMEM_B>>>(out);

    // 4. Causal softmax in place
    softmax_kernel<<<B_ * H_ * S_, 256>>>(out);
}

// round 7
// speedup vs baseline: 2.0269x; 1.0114x over previous
#include <cuda_runtime.h>
#include <cuda_bf16.h>
#include <mma.h>
#include <cstdint>

using namespace nvcuda;

// Problem constants
constexpr int B_   = 4;
constexpr int S_   = 1024;
constexpr int HID_ = 1024;
constexpr int H_   = 16;
constexpr int D_   = 64;

constexpr int M_ = B_ * S_;    // 4096 GEMM rows
constexpr int N_ = 2 * HID_;   // 2048 (Wq || Wk output dims)
constexpr int K_ = HID_;       // 1024 reduction

// Scratch: projected Q/K in [b, h, s, d] fp32 (pre-RoPE)
__device__ float4 g_q4[(size_t)B_ * H_ * S_ * D_ / 4];
__device__ float4 g_k4[(size_t)B_ * H_ * S_ * D_ / 4];
// bf16 hi/lo split operands for the tensor-core projection GEMM
__device__ __nv_bfloat16 g_a_hi[(size_t)M_ * K_];
__device__ __nv_bfloat16 g_a_lo[(size_t)M_ * K_];
__device__ __nv_bfloat16 g_b_hi[(size_t)N_ * K_];
__device__ __nv_bfloat16 g_b_lo[(size_t)N_ * K_];
// bf16 hi/lo RoPE'd Q/K for the tensor-core scores GEMM, [bh, s, d]
__device__ __nv_bfloat16 g_qh[(size_t)B_ * H_ * S_ * D_];
__device__ __nv_bfloat16 g_ql[(size_t)B_ * H_ * S_ * D_];
__device__ __nv_bfloat16 g_kh[(size_t)B_ * H_ * S_ * D_];
__device__ __nv_bfloat16 g_kl[(size_t)B_ * H_ * S_ * D_];

// ---------------------------------------------------------------------------
// cp.async helpers (baseline ISA, sm_80+)
// ---------------------------------------------------------------------------
__device__ __forceinline__ uint32_t smem_u32(const void* p) {
    uint32_t a;
    asm("{ .reg .u64 t; cvta.to.shared.u64 t, %1; cvt.u32.u64 %0, t; }"
        : "=r"(a) : "l"(p));
    return a;
}
__device__ __forceinline__ void cp_async16(uint32_t dst, const void* src) {
    asm volatile("cp.async.cg.shared.global [%0], [%1], 16;"
                 :: "r"(dst), "l"(src) : "memory");
}
__device__ __forceinline__ void cp_commit() {
    asm volatile("cp.async.commit_group;" ::: "memory");
}
template<int N>
__device__ __forceinline__ void cp_wait() {
    asm volatile("cp.async.wait_group %0;" :: "n"(N) : "memory");
}

// ---------------------------------------------------------------------------
// Kernel 0: split fp32 -> bf16 hi/lo for hidden (A) and Wq||Wk (B).
// ---------------------------------------------------------------------------
__global__ __launch_bounds__(256) void split_kernel(
    const float* __restrict__ hidden,
    const float* __restrict__ Wq,
    const float* __restrict__ Wk)
{
    const int a4 = M_ * K_ / 4;
    const int w4 = HID_ * K_ / 4;
    int i4 = blockIdx.x * blockDim.x + threadIdx.x;

    const float* src;
    __nv_bfloat16 *hi, *lo;
    size_t off;
    if (i4 < a4)           { src = hidden; off = (size_t)i4 * 4;        hi = g_a_hi; lo = g_a_lo; }
    else if (i4 < a4 + w4) { src = Wq;     off = (size_t)(i4 - a4) * 4; hi = g_b_hi; lo = g_b_lo; }
    else                   { src = Wk;     off = (size_t)(i4 - a4 - w4) * 4;
                             hi = g_b_hi + (size_t)HID_ * K_; lo = g_b_lo + (size_t)HID_ * K_; }

    float4 v = *(const float4*)(src + off);
    __nv_bfloat16 h0 = __float2bfloat16_rn(v.x);
    __nv_bfloat16 h1 = __float2bfloat16_rn(v.y);
    __nv_bfloat16 h2 = __float2bfloat16_rn(v.z);
    __nv_bfloat16 h3 = __float2bfloat16_rn(v.w);
    __nv_bfloat16 l0 = __float2bfloat16_rn(v.x - __bfloat162float(h0));
    __nv_bfloat16 l1 = __float2bfloat16_rn(v.y - __bfloat162float(h1));
    __nv_bfloat16 l2 = __float2bfloat16_rn(v.z - __bfloat162float(h2));
    __nv_bfloat16 l3 = __float2bfloat16_rn(v.w - __bfloat162float(h3));

    ushort4 hv, lv;
    hv.x = *(unsigned short*)&h0; hv.y = *(unsigned short*)&h1;
    hv.z = *(unsigned short*)&h2; hv.w = *(unsigned short*)&h3;
    lv.x = *(unsigned short*)&l0; lv.y = *(unsigned short*)&l1;
    lv.z = *(unsigned short*)&l2; lv.w = *(unsigned short*)&l3;
    *(ushort4*)(hi + off) = hv;
    *(ushort4*)(lo + off) = lv;
}

// ---------------------------------------------------------------------------
// Kernel 1: projection GEMM on WMMA bf16 (hi/lo 3-product, fp32 accum).
// Block tile 64x128, 4 warps, warp tile 32x64. 2-stage cp.async pipeline.
// ---------------------------------------------------------------------------
constexpr int BM  = 64;
constexpr int BN  = 128;
constexpr int BK  = 32;
constexpr int LDP = 40;

constexpr int AS_E     = 2 * 2 * BM * LDP;
constexpr int BS_E     = 2 * 2 * BN * LDP;
constexpr int P_SMEM_B = (AS_E + BS_E) * 2;

__device__ __forceinline__ int as_off(int st, int hl, int r, int cc) {
    return ((st * 2 + hl) * BM + r) * LDP + cc;
}
__device__ __forceinline__ int bs_off(int st, int hl, int r, int cc) {
    return AS_E + ((st * 2 + hl) * BN + r) * LDP + cc;
}

__global__ __launch_bounds__(128) void proj_mma_kernel()
{
    extern __shared__ __nv_bfloat16 psm[];

    const int tid = threadIdx.x;
    const int wid = tid >> 5;
    const int wm  = wid & 1;
    const int wn  = wid >> 1;

    const int n0 = blockIdx.x * BN;
    const int m0 = blockIdx.y * BM;

    auto load_stage = [&](int st, int kc) {
        #pragma unroll
        for (int p = 0; p < 4; p++) {
            int idx = tid + p * 128;
            int hl  = idx >> 8;
            int i2  = idx & 255;
            int r   = i2 >> 2;
            int c8  = (i2 & 3) * 8;
            const __nv_bfloat16* src = hl ? g_a_lo : g_a_hi;
            cp_async16(smem_u32(&psm[as_off(st, hl, r, c8)]),
                       src + (size_t)(m0 + r) * K_ + kc + c8);
        }
        #pragma unroll
        for (int p = 0; p < 8; p++) {
            int idx = tid + p * 128;
            int hl  = idx >> 9;
            int i2  = idx & 511;
            int r   = i2 >> 2;
            int c8  = (i2 & 3) * 8;
            const __nv_bfloat16* src = hl ? g_b_lo : g_b_hi;
            cp_async16(smem_u32(&psm[bs_off(st, hl, r, c8)]),
                       src + (size_t)(n0 + r) * K_ + kc + c8);
        }
    };

    wmma::fragment<wmma::accumulator, 16, 16, 16, float> c[2][4];
    #pragma unroll
    for (int i = 0; i < 2; i++)
        #pragma unroll
        for (int j = 0; j < 4; j++) wmma::fill_fragment(c[i][j], 0.0f);

    constexpr int NCH = K_ / BK;
    load_stage(0, 0);
    cp_commit();

    for (int ch = 0; ch < NCH; ch++) {
        const int st = ch & 1;
        if (ch + 1 < NCH) {
            load_stage(st ^ 1, (ch + 1) * BK);
            cp_commit();
            cp_wait<1>();
        } else {
            cp_wait<0>();
        }
        __syncthreads();

        #pragma unroll
        for (int ks = 0; ks < 2; ks++) {
            wmma::fragment<wmma::matrix_a, 16, 16, 16, __nv_bfloat16, wmma::row_major> ah[2], al[2];
            #pragma unroll
            for (int i = 0; i < 2; i++) {
                wmma::load_matrix_sync(ah[i], &psm[as_off(st, 0, wm * 32 + i * 16, ks * 16)], LDP);
                wmma::load_matrix_sync(al[i], &psm[as_off(st, 1, wm * 32 + i * 16, ks * 16)], LDP);
            }
            #pragma unroll
            for (int j = 0; j < 4; j++) {
                wmma::fragment<wmma::matrix_b, 16, 16, 16, __nv_bfloat16, wmma::col_major> bh, bl;
                wmma::load_matrix_sync(bh, &psm[bs_off(st, 0, wn * 64 + j * 16, ks * 16)], LDP);
                wmma::load_matrix_sync(bl, &psm[bs_off(st, 1, wn * 64 + j * 16, ks * 16)], LDP);
                #pragma unroll
                for (int i = 0; i < 2; i++) {
                    wmma::mma_sync(c[i][j], ah[i], bh, c[i][j]);
                    wmma::mma_sync(c[i][j], ah[i], bl, c[i][j]);
                    wmma::mma_sync(c[i][j], al[i], bh, c[i][j]);
                }
            }
        }
        __syncthreads();
    }

    float* outp   = (n0 < HID_) ? (float*)g_q4 : (float*)g_k4;
    const int nl0 = n0 & (HID_ - 1);

    #pragma unroll
    for (int i = 0; i < 2; i++) {
        const int m = m0 + wm * 32 + i * 16;
        const int b = m >> 10;
        const int s = m & (S_ - 1);
        #pragma unroll
        for (int j = 0; j < 4; j++) {
            const int nl = nl0 + wn * 64 + j * 16;
            const int h  = nl >> 6;
            const int d  = nl & 63;
            float* ptr = outp + (((size_t)(b * H_ + h) * S_ + s) * D_ + d);
            wmma::store_matrix_sync(ptr, c[i][j], D_, wmma::mem_row_major);
        }
    }
}

// ---------------------------------------------------------------------------
// Kernel 2: RoPE + bf16 hi/lo split.
// ---------------------------------------------------------------------------
__device__ __forceinline__ void split_store(__nv_bfloat16* hi, __nv_bfloat16* lo,
                                            size_t idx, float v) {
    __nv_bfloat16 h = __float2bfloat16_rn(v);
    __nv_bfloat16 l = __float2bfloat16_rn(v - __bfloat162float(h));
    hi[idx] = h; lo[idx] = l;
}

__global__ __launch_bounds__(256) void rope_split_kernel(
    const float* __restrict__ cosp,
    const float* __restrict__ sinp)
{
    int idx = blockIdx.x * blockDim.x + threadIdx.x;
    int d2     = idx & 31;
    int rowidx = idx >> 5;
    int s      = rowidx & (S_ - 1);

    float c  = cosp[s * D_ + d2];
    float sn = sinp[s * D_ + d2];

    const float* gq = (const float*)g_q4;
    const float* gk = (const float*)g_k4;
    size_t base = (size_t)rowidx * D_;

    float q1 = gq[base + d2], q2 = gq[base + d2 + 32];
    float qr1 = fmaf(q1, c, -q2 * sn);
    float qr2 = fmaf(q2, c,  q1 * sn);
    split_store(g_qh, g_ql, base + d2,      qr1);
    split_store(g_qh, g_ql, base + d2 + 32, qr2);

    float k1 = gk[base + d2], k2 = gk[base + d2 + 32];
    float kr1 = fmaf(k1, c, -k2 * sn);
    float kr2 = fmaf(k2, c,  k1 * sn);
    split_store(g_kh, g_kl, base + d2,      kr1);
    split_store(g_kh, g_kl, base + d2 + 32, kr2);
}

// ---------------------------------------------------------------------------
// Kernel 3 (FUSED): scores GEMM + causal softmax.
// One CTA per (bh, 32-row q group). Scores row block (32 x 1024 fp32) lives in
// shared memory; K tiles stream through a 2-stage cp.async pipeline; softmax
// is computed from smem and ONLY the final probabilities are written to DRAM.
// 256 threads, 8 warps: MMA warp grid 2(q:16) x 4(k:32).
// ---------------------------------------------------------------------------
constexpr int QR    = 32;          // q rows per CTA
constexpr int FLD   = 72;          // bf16 tile leading dim (64+8)
constexpr int SCLD  = 1032;        // scores smem leading dim (1024+8)

// smem layout (bytes)
constexpr int SC_B   = QR * SCLD * 4;                 // 132096 scores
constexpr int QT_B   = 2 * QR * FLD * 2;              // 9216   Q hi/lo
constexpr int KT_B   = 2 * 2 * 128 * FLD * 2;         // 73728  K hi/lo, 2 stages
constexpr int F_SMEM = SC_B + QT_B + KT_B;            // 215040

__global__ __launch_bounds__(256) void fused_scores_softmax_kernel(float* __restrict__ out)
{
    extern __shared__ char fsm[];
    float*         sc = (float*)fsm;                                   // [QR][SCLD]
    __nv_bfloat16* qt = (__nv_bfloat16*)(fsm + SC_B);                  // [hl][QR][FLD]
    __nv_bfloat16* kt = (__nv_bfloat16*)(fsm + SC_B + QT_B);           // [st][hl][128][FLD]

    const int bh = blockIdx.y;
    const int qg = 31 - blockIdx.x;        // heavy q groups scheduled first
    const int q0 = qg * QR;
    const int ktmax = q0 >> 7;             // last needed 128-wide k tile

    const int tid = threadIdx.x;
    const int wid = tid >> 5;
    const int lid = tid & 31;
    const int wq  = wid & 1;               // 2 warps over q (16 rows)
    const int wk  = wid >> 1;              // 4 warps over k (32 cols)

    const size_t qbase = (size_t)bh * S_ * D_ + (size_t)q0 * D_;
    const size_t kbase = (size_t)bh * S_ * D_;

    // ---- load Q rows (hi+lo): 2*32 rows * 8 chunks(16B) = 512 -> 2/thread ----
    #pragma unroll
    for (int p = 0; p < 2; p++) {
        int idx = tid + p * 256;
        int hl  = idx >> 8;
        int i2  = idx & 255;
        int r   = i2 >> 3;
        int c8  = (i2 & 7) * 8;
        const __nv_bfloat16* src = hl ? g_ql : g_qh;
        cp_async16(smem_u32(&qt[(hl * QR + r) * FLD + c8]),
                   src + qbase + (size_t)r * D_ + c8);
    }

    // K tile async loader: 2*128 rows * 8 chunks = 2048 -> 8/thread
    auto load_k = [&](int st, int tile) {
        const size_t tb = kbase + (size_t)tile * 128 * D_;
        #pragma unroll
        for (int p = 0; p < 8; p++) {
            int idx = tid + p * 256;
            int hl  = idx >> 10;
            int i2  = idx & 1023;
            int r   = i2 >> 3;
            int c8  = (i2 & 7) * 8;
            const __nv_bfloat16* src = hl ? g_kl : g_kh;
            cp_async16(smem_u32(&kt[((st * 2 + hl) * 128 + r) * FLD + c8]),
                       src + tb + (size_t)r * D_ + c8);
        }
    };

    load_k(0, 0);
    cp_commit();

    // ---- MMA over needed k tiles ----
    for (int t = 0; t <= ktmax; t++) {
        const int st = t & 1;
        if (t + 1 <= ktmax) {
            load_k(st ^ 1, t + 1);
            cp_commit();
            cp_wait<1>();
        } else {
            cp_wait<0>();
        }
        __syncthreads();

        wmma::fragment<wmma::accumulator, 16, 16, 16, float> c[2];
        #pragma unroll
        for (int j = 0; j < 2; j++) wmma::fill_fragment(c[j], 0.0f);

        #pragma unroll
        for (int ks = 0; ks < 4; ks++) {
            wmma::fragment<wmma::matrix_a, 16, 16, 16, __nv_bfloat16, wmma::row_major> ah, al;
            wmma::load_matrix_sync(ah, &qt[(0 * QR + wq * 16) * FLD + ks * 16], FLD);
            wmma::load_matrix_sync(al, &qt[(1 * QR + wq * 16) * FLD + ks * 16], FLD);
            #pragma unroll
            for (int j = 0; j < 2; j++) {
                const int kr = wk * 32 + j * 16;
                wmma::fragment<wmma::matrix_b, 16, 16, 16, __nv_bfloat16, wmma::col_major> bhf, blf;
                wmma::load_matrix_sync(bhf, &kt[((st * 2 + 0) * 128 + kr) * FLD + ks * 16], FLD);
                wmma::load_matrix_sync(blf, &kt[((st * 2 + 1) * 128 + kr) * FLD + ks * 16], FLD);
                wmma::mma_sync(c[j], ah, bhf, c[j]);
                wmma::mma_sync(c[j], ah, blf, c[j]);
                wmma::mma_sync(c[j], al, bhf, c[j]);
            }
        }

        // store raw scores into smem block
        #pragma unroll
        for (int j = 0; j < 2; j++) {
            float* dst = &sc[(wq * 16) * SCLD + t * 128 + wk * 32 + j * 16];
            wmma::store_matrix_sync(dst, c[j], SCLD, wmma::mem_row_major);
        }
        __syncthreads();   // stage st fully consumed before it is reloaded
    }

    // ---- softmax from smem, write final probabilities (one warp per row) ----
    for (int rr = wid; rr < QR; rr += 8) {
        const int qrow   = q0 + rr;
        const int nvalid = qrow + 1;
        const float* srow = &sc[rr * SCLD];

        float v[32];
        float m = -3.402823466e38f;
        #pragma unroll
        for (int i = 0; i < 8; i++) {
            const int col = lid * 4 + i * 128;
            float4 f = *(const float4*)(srow + col);
            v[i * 4 + 0] = f.x; v[i * 4 + 1] = f.y;
            v[i * 4 + 2] = f.z; v[i * 4 + 3] = f.w;
            #pragma unroll
            for (int e = 0; e < 4; e++)
                if (col + e < nvalid) m = fmaxf(m, v[i * 4 + e]);
        }
        #pragma unroll
        for (int o = 16; o > 0; o >>= 1)
            m = fmaxf(m, __shfl_xor_sync(0xFFFFFFFFu, m, o));
        m *= 0.125f;   // scores are raw; softmax over scaled values

        float ssum = 0.f;
        float ev[32];
        #pragma unroll
        for (int i = 0; i < 8; i++) {
            const int col = lid * 4 + i * 128;
            #pragma unroll
            for (int e = 0; e < 4; e++) {
                float ex = (col + e < nvalid) ? __expf(fmaf(v[i * 4 + e], 0.125f, -m)) : 0.f;
                ev[i * 4 + e] = ex;
                ssum += ex;
            }
        }
        #pragma unroll
        for (int o = 16; o > 0; o >>= 1)
            ssum += __shfl_xor_sync(0xFFFFFFFFu, ssum, o);
        const float inv = 1.0f / ssum;

        float* orow = out + ((size_t)bh * S_ + qrow) * S_;
        #pragma unroll
        for (int i = 0; i < 8; i++) {
            const int col = lid * 4 + i * 128;
            float4 f = make_float4(ev[i * 4 + 0] * inv, ev[i * 4 + 1] * inv,
                                   ev[i * 4 + 2] * inv, ev[i * 4 + 3] * inv);
            *(float4*)(orow + col) = f;
        }
    }
}

// ---------------------------------------------------------------------------
// Launch
// ---------------------------------------------------------------------------
extern "C" void kernel_launch(void* const* d_in, const int* in_sizes, int n_in,
                              void* d_out, int out_size)
{
    const float* hidden = (const float*)d_in[0];
    const float* cosp   = (const float*)d_in[1];
    const float* sinp   = (const float*)d_in[2];
    const float* Wq     = (const float*)d_in[n_in - 2];
    const float* Wk     = (const float*)d_in[n_in - 1];
    float* out          = (float*)d_out;

    // Idempotent attribute setters (no static guards per harness rules).
    cudaFuncSetAttribute(proj_mma_kernel,
                         cudaFuncAttributeMaxDynamicSharedMemorySize, P_SMEM_B);
    cudaFuncSetAttribute(fused_scores_softmax_kernel,
                         cudaFuncAttributeMaxDynamicSharedMemorySize, F_SMEM);

    // 0. fp32 -> bf16 hi/lo split of A and W
    int total4 = (M_ * K_ + N_ * K_) / 4;
    split_kernel<<<total4 / 256, 256>>>(hidden, Wq, Wk);

    // 1. Projection GEMM on tensor cores
    dim3 g1(N_ / BN, M_ / BM);
    proj_mma_kernel<<<g1, 128, P_SMEM_B>>>();

    // 2. RoPE + hi/lo split for scores operands
    rope_split_kernel<<<(B_ * H_ * S_ * 32) / 256, 256>>>(cosp, sinp);

    // 3. Fused scores GEMM + causal softmax -> final probabilities
    dim3 g3(S_ / QR, B_ * H_);
    fused_scores_softmax_kernel<<<g3, 256, F_SMEM>>>(out);
}